// round 11
// baseline (speedup 1.0000x reference)
#include <cuda_runtime.h>
#include <cuda_bf16.h>
#include <cstdint>

#define B_SZ   2048
#define L_SZ   200000
#define H_SZ   64

#define BM 128
#define BN 128
#define NTHREADS 256
#define GX ((L_SZ + BN - 1) / BN)   // 1563
#define NY (B_SZ / BM)              // 16
#define TILE_BYTES (BM * 128)       // 16384

#define SWZ128(off) ((off) ^ (((off) >> 3) & 0x70))

__device__ float g_partial[(size_t)GX * B_SZ];
__device__ float g_terms[B_SZ];
__device__ __align__(16) uint4 g_atile[B_SZ * 8];   // pre-swizzled bf16 A tiles, 262KB

// ---------------------------------------------------------------------------
__device__ __forceinline__ uint32_t smem_u32(const void* p) {
    uint32_t a;
    asm("{ .reg .u64 t; cvta.to.shared.u64 t, %1; cvt.u32.u64 %0, t; }"
        : "=r"(a) : "l"(p));
    return a;
}
__device__ __forceinline__ void ldm_x4(uint32_t& r0, uint32_t& r1,
                                       uint32_t& r2, uint32_t& r3, uint32_t addr) {
    asm volatile("ldmatrix.sync.aligned.m8n8.x4.shared.b16 {%0,%1,%2,%3}, [%4];"
                 : "=r"(r0), "=r"(r1), "=r"(r2), "=r"(r3) : "r"(addr));
}
__device__ __forceinline__ void ldm_x2(uint32_t& r0, uint32_t& r1, uint32_t addr) {
    asm volatile("ldmatrix.sync.aligned.m8n8.x2.shared.b16 {%0,%1}, [%2];"
                 : "=r"(r0), "=r"(r1) : "r"(addr));
}
__device__ __forceinline__ void mma_bf16(float* d, const uint32_t* a, const uint32_t* bfr) {
    asm volatile(
        "mma.sync.aligned.m16n8k16.row.col.f32.bf16.bf16.f32 "
        "{%0,%1,%2,%3}, {%4,%5,%6,%7}, {%8,%9}, {%0,%1,%2,%3};"
        : "+f"(d[0]), "+f"(d[1]), "+f"(d[2]), "+f"(d[3])
        : "r"(a[0]), "r"(a[1]), "r"(a[2]), "r"(a[3]), "r"(bfr[0]), "r"(bfr[1]));
}
__device__ __forceinline__ float htanh(float v) {
    float t;
    asm("tanh.approx.f32 %0, %1;" : "=f"(t) : "f"(v));
    return t;
}
// exp(0.5 + 0.5*t), t in (-1,1): degree-4 in t, coeffs e^0.5 * 0.5^k / k!
__device__ __forceinline__ float exp_sig_from_t(float t) {
    float p = 4.2936190e-3f;
    p = fmaf(p, t, 3.4348952e-2f);
    p = fmaf(p, t, 2.0609371e-1f);
    p = fmaf(p, t, 8.2436064e-1f);
    p = fmaf(p, t, 1.6487213e0f);
    return p;
}
__device__ __forceinline__ uint4 pack_bf16(float4 v0, float4 v1) {
    uint4 u;
    __nv_bfloat162 t;
    t = __float22bfloat162_rn(make_float2(v0.x, v0.y)); u.x = *(uint32_t*)&t;
    t = __float22bfloat162_rn(make_float2(v0.z, v0.w)); u.y = *(uint32_t*)&t;
    t = __float22bfloat162_rn(make_float2(v1.x, v1.y)); u.z = *(uint32_t*)&t;
    t = __float22bfloat162_rn(make_float2(v1.z, v1.w)); u.w = *(uint32_t*)&t;
    return u;
}

#define CP_ASYNC16(dst, src) \
    asm volatile("cp.async.cg.shared.global [%0], [%1], 16;" :: "r"(dst), "l"(src))
#define CP_COMMIT() asm volatile("cp.async.commit_group;" ::: "memory")
#define CP_WAIT(n)  asm volatile("cp.async.wait_group %0;" :: "n"(n) : "memory")

// ---------------------------------------------------------------------------
// Kernel 1: gather return_embed + build pre-swizzled bf16 A tiles.
// ---------------------------------------------------------------------------
__global__ void prep_kernel(const int* __restrict__ label,
                            const float* __restrict__ table,
                            float* __restrict__ out_embed) {
    int m = blockIdx.x * blockDim.x + threadIdx.x;
    if (m >= B_SZ) return;
    int lab = label[m];
    const float4* src = reinterpret_cast<const float4*>(table + (size_t)lab * H_SZ);
    float* dst = out_embed + (size_t)m * H_SZ;

    char* tile = reinterpret_cast<char*>(g_atile) + (m >> 7) * TILE_BYTES;
    int r = m & 127;
    #pragma unroll
    for (int ch = 0; ch < 8; ch++) {
        float4 v0 = __ldg(src + ch * 2);
        float4 v1 = __ldg(src + ch * 2 + 1);
        reinterpret_cast<float*>(dst)[ch * 8 + 0] = v0.x;
        reinterpret_cast<float*>(dst)[ch * 8 + 1] = v0.y;
        reinterpret_cast<float*>(dst)[ch * 8 + 2] = v0.z;
        reinterpret_cast<float*>(dst)[ch * 8 + 3] = v0.w;
        reinterpret_cast<float*>(dst)[ch * 8 + 4] = v1.x;
        reinterpret_cast<float*>(dst)[ch * 8 + 5] = v1.y;
        reinterpret_cast<float*>(dst)[ch * 8 + 6] = v1.z;
        reinterpret_cast<float*>(dst)[ch * 8 + 7] = v1.w;
        uint32_t off = r * 128 + ch * 16;
        *reinterpret_cast<uint4*>(tile + SWZ128(off)) = pack_bf16(v0, v1);
    }
}

// ---------------------------------------------------------------------------
// Kernel 2: bf16 mma.sync GEMM + sigmoid epilogue; A tiles streamed by
// cp.async (double-buffered, 2 tiles in flight), R8 schedule.
// Single change vs R8: per-CTA uniform bounds branch in the epilogue.
// ---------------------------------------------------------------------------
__global__ __launch_bounds__(NTHREADS, 2)
void logits_kernel(const float* __restrict__ W,
                   const float* __restrict__ b,
                   float* __restrict__ out) {
    __shared__ __align__(1024) char w_s[BN * 128];
    __shared__ __align__(1024) char a_s[2][TILE_BYTES];
    __shared__ float bia_s[BN];      // b/2
    __shared__ float red_s[BM][4];

    const int tid  = threadIdx.x;
    const int wid  = tid >> 5;
    const int lane = tid & 31;
    const int bx   = blockIdx.x;
    const int nblk = bx * BN;
    const bool all_valid = (nblk + BN <= L_SZ);

    const uint32_t w_base = smem_u32(w_s);
    const int wm = (wid & 1) * 64;
    const int wn = (wid >> 1) * 32;

    const char* atile_g = reinterpret_cast<const char*>(g_atile);

    // ---- W tile + half-bias ----
    for (int idx = tid; idx < BN * 8; idx += NTHREADS) {
        int r = idx >> 3, ch = idx & 7;
        int n = nblk + r;
        uint32_t off = r * 128 + ch * 16;
        if (n < L_SZ) {
            const float4* src = reinterpret_cast<const float4*>(W + (size_t)n * H_SZ);
            *reinterpret_cast<uint4*>(w_s + SWZ128(off)) =
                pack_bf16(__ldg(src + ch * 2), __ldg(src + ch * 2 + 1));
        } else {
            *reinterpret_cast<uint4*>(w_s + SWZ128(off)) = make_uint4(0, 0, 0, 0);
        }
    }
    for (int idx = tid; idx < BN; idx += NTHREADS) {
        int n = nblk + idx;
        bia_s[idx] = (n < L_SZ) ? 0.5f * __ldg(&b[n]) : 0.0f;
    }

    // ---- cp.async prologue: tiles 0 and 1 in flight ----
    {
        const uint32_t d0 = smem_u32(a_s[0]) + tid * 16;
        const uint32_t d1 = smem_u32(a_s[1]) + tid * 16;
        #pragma unroll
        for (int i = 0; i < 4; i++)
            CP_ASYNC16(d0 + i * NTHREADS * 16,
                       atile_g + 0 * TILE_BYTES + tid * 16 + i * NTHREADS * 16);
        CP_COMMIT();
        #pragma unroll
        for (int i = 0; i < 4; i++)
            CP_ASYNC16(d1 + i * NTHREADS * 16,
                       atile_g + 1 * TILE_BYTES + tid * 16 + i * NTHREADS * 16);
        CP_COMMIT();
    }

    float bh0[4], bh1[4];

    for (int y = 0; y < NY; y++) {
        const int mblk = y * BM;
        const int buf = y & 1;
        const uint32_t a_base = smem_u32(a_s[buf]);

        if (y < NY - 1) CP_WAIT(1); else CP_WAIT(0);
        __syncthreads();

        if (y == 0) {   // bia_s now visible
            #pragma unroll
            for (int j = 0; j < 4; j++) {
                int col = wn + j * 8 + (lane & 3) * 2;
                bh0[j] = bia_s[col];
                bh1[j] = bia_s[col + 1];
            }
        }

        // ---- MMA mainloop: 4 k-steps of 16 ----
        float acc[4][4][4];
        #pragma unroll
        for (int i = 0; i < 4; i++)
            #pragma unroll
            for (int j = 0; j < 4; j++)
                #pragma unroll
                for (int e = 0; e < 4; e++) acc[i][j][e] = 0.0f;

        #pragma unroll
        for (int ks = 0; ks < 4; ks++) {
            uint32_t a[4][4];
            #pragma unroll
            for (int i = 0; i < 4; i++) {
                uint32_t off = (uint32_t)(wm + i * 16 + (lane & 15)) * 128
                             + ks * 32 + (lane >> 4) * 16;
                ldm_x4(a[i][0], a[i][1], a[i][2], a[i][3], a_base + SWZ128(off));
            }
            uint32_t bf[4][2];
            #pragma unroll
            for (int j = 0; j < 4; j++) {
                uint32_t off = (uint32_t)(wn + j * 8 + (lane & 7)) * 128
                             + ks * 32 + ((lane >> 3) & 1) * 16;
                ldm_x2(bf[j][0], bf[j][1], w_base + SWZ128(off));
            }
            #pragma unroll
            for (int i = 0; i < 4; i++)
                #pragma unroll
                for (int j = 0; j < 4; j++)
                    mma_bf16(acc[i][j], a[i], bf[j]);
        }

        // ---- Epilogue: hoisted uniform bounds branch ----
        float ex0[4], ex1[4];
        #pragma unroll
        for (int i = 0; i < 4; i++) { ex0[i] = 0.0f; ex1[i] = 0.0f; }

        if (all_valid) {
            #pragma unroll
            for (int i = 0; i < 4; i++) {
                const int r0 = wm + i * 16 + (lane >> 2);
                const int r1 = r0 + 8;
                #pragma unroll
                for (int j = 0; j < 4; j++) {
                    const int gn = nblk + wn + j * 8 + (lane & 3) * 2;
                    float t00 = htanh(fmaf(acc[i][j][0], 0.5f, bh0[j]));
                    float t01 = htanh(fmaf(acc[i][j][1], 0.5f, bh1[j]));
                    float t10 = htanh(fmaf(acc[i][j][2], 0.5f, bh0[j]));
                    float t11 = htanh(fmaf(acc[i][j][3], 0.5f, bh1[j]));
                    __stcs(reinterpret_cast<float2*>(&out[(size_t)(mblk + r0) * L_SZ + gn]),
                           make_float2(fmaf(0.5f, t00, 0.5f), fmaf(0.5f, t01, 0.5f)));
                    __stcs(reinterpret_cast<float2*>(&out[(size_t)(mblk + r1) * L_SZ + gn]),
                           make_float2(fmaf(0.5f, t10, 0.5f), fmaf(0.5f, t11, 0.5f)));
                    ex0[i] += exp_sig_from_t(t00) + exp_sig_from_t(t01);
                    ex1[i] += exp_sig_from_t(t10) + exp_sig_from_t(t11);
                }
            }
        } else {
            #pragma unroll
            for (int i = 0; i < 4; i++) {
                const int r0 = wm + i * 16 + (lane >> 2);
                const int r1 = r0 + 8;
                #pragma unroll
                for (int j = 0; j < 4; j++) {
                    const int gn = nblk + wn + j * 8 + (lane & 3) * 2;
                    float t00 = htanh(fmaf(acc[i][j][0], 0.5f, bh0[j]));
                    float t01 = htanh(fmaf(acc[i][j][1], 0.5f, bh1[j]));
                    float t10 = htanh(fmaf(acc[i][j][2], 0.5f, bh0[j]));
                    float t11 = htanh(fmaf(acc[i][j][3], 0.5f, bh1[j]));
                    if (gn < L_SZ) {
                        __stcs(reinterpret_cast<float2*>(&out[(size_t)(mblk + r0) * L_SZ + gn]),
                               make_float2(fmaf(0.5f, t00, 0.5f), fmaf(0.5f, t01, 0.5f)));
                        __stcs(reinterpret_cast<float2*>(&out[(size_t)(mblk + r1) * L_SZ + gn]),
                               make_float2(fmaf(0.5f, t10, 0.5f), fmaf(0.5f, t11, 0.5f)));
                        ex0[i] += exp_sig_from_t(t00) + exp_sig_from_t(t01);
                        ex1[i] += exp_sig_from_t(t10) + exp_sig_from_t(t11);
                    }
                }
            }
        }
        #pragma unroll
        for (int i = 0; i < 4; i++) {
            float v0 = ex0[i], v1 = ex1[i];
            v0 += __shfl_down_sync(0xffffffffu, v0, 2, 4);
            v0 += __shfl_down_sync(0xffffffffu, v0, 1, 4);
            v1 += __shfl_down_sync(0xffffffffu, v1, 2, 4);
            v1 += __shfl_down_sync(0xffffffffu, v1, 1, 4);
            if ((lane & 3) == 0) {
                red_s[wm + i * 16 + (lane >> 2)][wid >> 1]     = v0;
                red_s[wm + i * 16 + (lane >> 2) + 8][wid >> 1] = v1;
            }
        }
        __syncthreads();   // a_s[buf] reads done; red_s complete

        // ---- Prefetch tile y+2 into a_s[buf] (now free) ----
        if (y + 2 < NY) {
            const uint32_t d = smem_u32(a_s[buf]) + tid * 16;
            #pragma unroll
            for (int i = 0; i < 4; i++)
                CP_ASYNC16(d + i * NTHREADS * 16,
                           atile_g + (size_t)(y + 2) * TILE_BYTES
                                   + tid * 16 + i * NTHREADS * 16);
            CP_COMMIT();
        }

        if (tid < BM) {
            float s = red_s[tid][0] + red_s[tid][1] + red_s[tid][2] + red_s[tid][3];
            g_partial[(size_t)bx * B_SZ + mblk + tid] = s;
        }
    }
}

// ---------------------------------------------------------------------------
// Kernel 3: fused deterministic row-sum + loss terms.
// ---------------------------------------------------------------------------
__global__ void rowsum_terms_kernel(const int* __restrict__ label,
                                    const float* __restrict__ logits) {
    int m = blockIdx.x * blockDim.x + threadIdx.x;
    if (m < B_SZ) {
        float s = 0.0f;
        for (int j = 0; j < GX; j++) s += g_partial[(size_t)j * B_SZ + m];
        g_terms[m] = logf(s) - logits[(size_t)m * L_SZ + label[m]];
    }
}

__global__ void loss_reduce_kernel(float* __restrict__ out_loss) {
    __shared__ float red[1024];
    int t = threadIdx.x;
    red[t] = g_terms[t] + g_terms[t + 1024];
    __syncthreads();
    for (int off = 512; off > 0; off >>= 1) {
        if (t < off) red[t] += red[t + off];
        __syncthreads();
    }
    if (t == 0) out_loss[0] = red[0] / (float)B_SZ;
}

// ---------------------------------------------------------------------------
extern "C" void kernel_launch(void* const* d_in, const int* in_sizes, int n_in,
                              void* d_out, int out_size) {
    const int*   label = (const int*)d_in[0];
    const float* table = (const float*)d_in[1];
    const float* W     = (const float*)d_in[2];
    const float* b     = (const float*)d_in[3];
    float* out = (float*)d_out;

    float* out_logits = out;
    float* out_loss   = out + (size_t)B_SZ * L_SZ;
    float* out_embed  = out + (size_t)B_SZ * L_SZ + 1;

    prep_kernel<<<(B_SZ + 255) / 256, 256>>>(label, table, out_embed);
    logits_kernel<<<GX, NTHREADS>>>(W, b, out_logits);
    rowsum_terms_kernel<<<(B_SZ + 255) / 256, 256>>>(label, out_logits);
    loss_reduce_kernel<<<1, 1024>>>(out_loss);
}

// round 12
// speedup vs baseline: 1.0287x; 1.0287x over previous
#include <cuda_runtime.h>
#include <cuda_bf16.h>
#include <cstdint>

#define B_SZ   2048
#define L_SZ   200000
#define H_SZ   64

#define BM 128
#define BN 128
#define NTHREADS 256
#define GX ((L_SZ + BN - 1) / BN)   // 1563
#define NY_TOT (B_SZ / BM)          // 16
#define MSPLIT 2
#define NY_PER (NY_TOT / MSPLIT)    // 8
#define TILE_BYTES (BM * 128)       // 16384

#define SWZ128(off) ((off) ^ (((off) >> 3) & 0x70))

__device__ float g_partial[(size_t)GX * B_SZ];
__device__ float g_terms[B_SZ];
__device__ __align__(16) uint4 g_atile[B_SZ * 8];   // pre-swizzled bf16 A tiles, 262KB

// ---------------------------------------------------------------------------
__device__ __forceinline__ uint32_t smem_u32(const void* p) {
    uint32_t a;
    asm("{ .reg .u64 t; cvta.to.shared.u64 t, %1; cvt.u32.u64 %0, t; }"
        : "=r"(a) : "l"(p));
    return a;
}
__device__ __forceinline__ void ldm_x4(uint32_t& r0, uint32_t& r1,
                                       uint32_t& r2, uint32_t& r3, uint32_t addr) {
    asm volatile("ldmatrix.sync.aligned.m8n8.x4.shared.b16 {%0,%1,%2,%3}, [%4];"
                 : "=r"(r0), "=r"(r1), "=r"(r2), "=r"(r3) : "r"(addr));
}
__device__ __forceinline__ void ldm_x2(uint32_t& r0, uint32_t& r1, uint32_t addr) {
    asm volatile("ldmatrix.sync.aligned.m8n8.x2.shared.b16 {%0,%1}, [%2];"
                 : "=r"(r0), "=r"(r1) : "r"(addr));
}
__device__ __forceinline__ void mma_bf16(float* d, const uint32_t* a, const uint32_t* bfr) {
    asm volatile(
        "mma.sync.aligned.m16n8k16.row.col.f32.bf16.bf16.f32 "
        "{%0,%1,%2,%3}, {%4,%5,%6,%7}, {%8,%9}, {%0,%1,%2,%3};"
        : "+f"(d[0]), "+f"(d[1]), "+f"(d[2]), "+f"(d[3])
        : "r"(a[0]), "r"(a[1]), "r"(a[2]), "r"(a[3]), "r"(bfr[0]), "r"(bfr[1]));
}
__device__ __forceinline__ float htanh(float v) {
    float t;
    asm("tanh.approx.f32 %0, %1;" : "=f"(t) : "f"(v));
    return t;
}
// exp(0.5 + 0.5*t), t in (-1,1): degree-4 in t, coeffs e^0.5 * 0.5^k / k!
__device__ __forceinline__ float exp_sig_from_t(float t) {
    float p = 4.2936190e-3f;
    p = fmaf(p, t, 3.4348952e-2f);
    p = fmaf(p, t, 2.0609371e-1f);
    p = fmaf(p, t, 8.2436064e-1f);
    p = fmaf(p, t, 1.6487213e0f);
    return p;
}
__device__ __forceinline__ uint4 pack_bf16(float4 v0, float4 v1) {
    uint4 u;
    __nv_bfloat162 t;
    t = __float22bfloat162_rn(make_float2(v0.x, v0.y)); u.x = *(uint32_t*)&t;
    t = __float22bfloat162_rn(make_float2(v0.z, v0.w)); u.y = *(uint32_t*)&t;
    t = __float22bfloat162_rn(make_float2(v1.x, v1.y)); u.z = *(uint32_t*)&t;
    t = __float22bfloat162_rn(make_float2(v1.z, v1.w)); u.w = *(uint32_t*)&t;
    return u;
}

#define CP_ASYNC16(dst, src) \
    asm volatile("cp.async.cg.shared.global [%0], [%1], 16;" :: "r"(dst), "l"(src))
#define CP_COMMIT() asm volatile("cp.async.commit_group;" ::: "memory")
#define CP_WAIT(n)  asm volatile("cp.async.wait_group %0;" :: "n"(n) : "memory")

// ---------------------------------------------------------------------------
// Kernel 1: gather return_embed + build pre-swizzled bf16 A tiles.
// ---------------------------------------------------------------------------
__global__ void prep_kernel(const int* __restrict__ label,
                            const float* __restrict__ table,
                            float* __restrict__ out_embed) {
    int m = blockIdx.x * blockDim.x + threadIdx.x;
    if (m >= B_SZ) return;
    int lab = label[m];
    const float4* src = reinterpret_cast<const float4*>(table + (size_t)lab * H_SZ);
    float* dst = out_embed + (size_t)m * H_SZ;

    char* tile = reinterpret_cast<char*>(g_atile) + (m >> 7) * TILE_BYTES;
    int r = m & 127;
    #pragma unroll
    for (int ch = 0; ch < 8; ch++) {
        float4 v0 = __ldg(src + ch * 2);
        float4 v1 = __ldg(src + ch * 2 + 1);
        reinterpret_cast<float*>(dst)[ch * 8 + 0] = v0.x;
        reinterpret_cast<float*>(dst)[ch * 8 + 1] = v0.y;
        reinterpret_cast<float*>(dst)[ch * 8 + 2] = v0.z;
        reinterpret_cast<float*>(dst)[ch * 8 + 3] = v0.w;
        reinterpret_cast<float*>(dst)[ch * 8 + 4] = v1.x;
        reinterpret_cast<float*>(dst)[ch * 8 + 5] = v1.y;
        reinterpret_cast<float*>(dst)[ch * 8 + 6] = v1.z;
        reinterpret_cast<float*>(dst)[ch * 8 + 7] = v1.w;
        uint32_t off = r * 128 + ch * 16;
        *reinterpret_cast<uint4*>(tile + SWZ128(off)) = pack_bf16(v0, v1);
    }
}

// ---------------------------------------------------------------------------
// Kernel 2: bf16 mma.sync GEMM + sigmoid epilogue; R8 loop body exactly;
// grid = (GX, MSPLIT), each CTA handles NY_PER m-tiles (wave-tail smoothing).
// ---------------------------------------------------------------------------
__global__ __launch_bounds__(NTHREADS, 2)
void logits_kernel(const float* __restrict__ W,
                   const float* __restrict__ b,
                   float* __restrict__ out) {
    __shared__ __align__(1024) char w_s[BN * 128];
    __shared__ __align__(1024) char a_s[2][TILE_BYTES];
    __shared__ float bia_s[BN];      // b/2
    __shared__ float red_s[BM][4];

    const int tid  = threadIdx.x;
    const int wid  = tid >> 5;
    const int lane = tid & 31;
    const int bx   = blockIdx.x;
    const int nblk = bx * BN;
    const int ybase = blockIdx.y * NY_PER;   // first m-tile index for this CTA

    const uint32_t w_base = smem_u32(w_s);
    const int wm = (wid & 1) * 64;
    const int wn = (wid >> 1) * 32;

    const char* atile_g = reinterpret_cast<const char*>(g_atile);

    // ---- W tile + half-bias ----
    for (int idx = tid; idx < BN * 8; idx += NTHREADS) {
        int r = idx >> 3, ch = idx & 7;
        int n = nblk + r;
        uint32_t off = r * 128 + ch * 16;
        if (n < L_SZ) {
            const float4* src = reinterpret_cast<const float4*>(W + (size_t)n * H_SZ);
            *reinterpret_cast<uint4*>(w_s + SWZ128(off)) =
                pack_bf16(__ldg(src + ch * 2), __ldg(src + ch * 2 + 1));
        } else {
            *reinterpret_cast<uint4*>(w_s + SWZ128(off)) = make_uint4(0, 0, 0, 0);
        }
    }
    for (int idx = tid; idx < BN; idx += NTHREADS) {
        int n = nblk + idx;
        bia_s[idx] = (n < L_SZ) ? 0.5f * __ldg(&b[n]) : 0.0f;
    }

    // ---- cp.async prologue: tiles ybase, ybase+1 in flight ----
    {
        const uint32_t d0 = smem_u32(a_s[0]) + tid * 16;
        const uint32_t d1 = smem_u32(a_s[1]) + tid * 16;
        #pragma unroll
        for (int i = 0; i < 4; i++)
            CP_ASYNC16(d0 + i * NTHREADS * 16,
                       atile_g + (size_t)ybase * TILE_BYTES
                               + tid * 16 + i * NTHREADS * 16);
        CP_COMMIT();
        #pragma unroll
        for (int i = 0; i < 4; i++)
            CP_ASYNC16(d1 + i * NTHREADS * 16,
                       atile_g + (size_t)(ybase + 1) * TILE_BYTES
                               + tid * 16 + i * NTHREADS * 16);
        CP_COMMIT();
    }

    float bh0[4], bh1[4];

    for (int y = 0; y < NY_PER; y++) {
        const int mblk = (ybase + y) * BM;
        const int buf = y & 1;
        const uint32_t a_base = smem_u32(a_s[buf]);

        if (y < NY_PER - 1) CP_WAIT(1); else CP_WAIT(0);
        __syncthreads();

        if (y == 0) {   // bia_s now visible
            #pragma unroll
            for (int j = 0; j < 4; j++) {
                int col = wn + j * 8 + (lane & 3) * 2;
                bh0[j] = bia_s[col];
                bh1[j] = bia_s[col + 1];
            }
        }

        // ---- MMA mainloop: 4 k-steps of 16 ----
        float acc[4][4][4];
        #pragma unroll
        for (int i = 0; i < 4; i++)
            #pragma unroll
            for (int j = 0; j < 4; j++)
                #pragma unroll
                for (int e = 0; e < 4; e++) acc[i][j][e] = 0.0f;

        #pragma unroll
        for (int ks = 0; ks < 4; ks++) {
            uint32_t a[4][4];
            #pragma unroll
            for (int i = 0; i < 4; i++) {
                uint32_t off = (uint32_t)(wm + i * 16 + (lane & 15)) * 128
                             + ks * 32 + (lane >> 4) * 16;
                ldm_x4(a[i][0], a[i][1], a[i][2], a[i][3], a_base + SWZ128(off));
            }
            uint32_t bf[4][2];
            #pragma unroll
            for (int j = 0; j < 4; j++) {
                uint32_t off = (uint32_t)(wn + j * 8 + (lane & 7)) * 128
                             + ks * 32 + ((lane >> 3) & 1) * 16;
                ldm_x2(bf[j][0], bf[j][1], w_base + SWZ128(off));
            }
            #pragma unroll
            for (int i = 0; i < 4; i++)
                #pragma unroll
                for (int j = 0; j < 4; j++)
                    mma_bf16(acc[i][j], a[i], bf[j]);
        }

        // ---- Epilogue (R8 form: per-store predicate) ----
        float ex0[4], ex1[4];
        #pragma unroll
        for (int i = 0; i < 4; i++) { ex0[i] = 0.0f; ex1[i] = 0.0f; }

        #pragma unroll
        for (int i = 0; i < 4; i++) {
            const int r0 = wm + i * 16 + (lane >> 2);
            const int r1 = r0 + 8;
            #pragma unroll
            for (int j = 0; j < 4; j++) {
                const int gn = nblk + wn + j * 8 + (lane & 3) * 2;
                float t00 = htanh(fmaf(acc[i][j][0], 0.5f, bh0[j]));
                float t01 = htanh(fmaf(acc[i][j][1], 0.5f, bh1[j]));
                float t10 = htanh(fmaf(acc[i][j][2], 0.5f, bh0[j]));
                float t11 = htanh(fmaf(acc[i][j][3], 0.5f, bh1[j]));
                if (gn < L_SZ) {
                    __stcs(reinterpret_cast<float2*>(&out[(size_t)(mblk + r0) * L_SZ + gn]),
                           make_float2(fmaf(0.5f, t00, 0.5f), fmaf(0.5f, t01, 0.5f)));
                    __stcs(reinterpret_cast<float2*>(&out[(size_t)(mblk + r1) * L_SZ + gn]),
                           make_float2(fmaf(0.5f, t10, 0.5f), fmaf(0.5f, t11, 0.5f)));
                    ex0[i] += exp_sig_from_t(t00) + exp_sig_from_t(t01);
                    ex1[i] += exp_sig_from_t(t10) + exp_sig_from_t(t11);
                }
            }
        }
        #pragma unroll
        for (int i = 0; i < 4; i++) {
            float v0 = ex0[i], v1 = ex1[i];
            v0 += __shfl_down_sync(0xffffffffu, v0, 2, 4);
            v0 += __shfl_down_sync(0xffffffffu, v0, 1, 4);
            v1 += __shfl_down_sync(0xffffffffu, v1, 2, 4);
            v1 += __shfl_down_sync(0xffffffffu, v1, 1, 4);
            if ((lane & 3) == 0) {
                red_s[wm + i * 16 + (lane >> 2)][wid >> 1]     = v0;
                red_s[wm + i * 16 + (lane >> 2) + 8][wid >> 1] = v1;
            }
        }
        __syncthreads();   // a_s[buf] reads done; red_s complete

        // ---- Prefetch tile y+2 into a_s[buf] (now free) ----
        if (y + 2 < NY_PER) {
            const uint32_t d = smem_u32(a_s[buf]) + tid * 16;
            #pragma unroll
            for (int i = 0; i < 4; i++)
                CP_ASYNC16(d + i * NTHREADS * 16,
                           atile_g + (size_t)(ybase + y + 2) * TILE_BYTES
                                   + tid * 16 + i * NTHREADS * 16);
            CP_COMMIT();
        }

        if (tid < BM) {
            float s = red_s[tid][0] + red_s[tid][1] + red_s[tid][2] + red_s[tid][3];
            g_partial[(size_t)bx * B_SZ + mblk + tid] = s;
        }
    }
}

// ---------------------------------------------------------------------------
// Kernel 3: fused deterministic row-sum + loss terms.
// ---------------------------------------------------------------------------
__global__ void rowsum_terms_kernel(const int* __restrict__ label,
                                    const float* __restrict__ logits) {
    int m = blockIdx.x * blockDim.x + threadIdx.x;
    if (m < B_SZ) {
        float s = 0.0f;
        for (int j = 0; j < GX; j++) s += g_partial[(size_t)j * B_SZ + m];
        g_terms[m] = logf(s) - logits[(size_t)m * L_SZ + label[m]];
    }
}

__global__ void loss_reduce_kernel(float* __restrict__ out_loss) {
    __shared__ float red[1024];
    int t = threadIdx.x;
    red[t] = g_terms[t] + g_terms[t + 1024];
    __syncthreads();
    for (int off = 512; off > 0; off >>= 1) {
        if (t < off) red[t] += red[t + off];
        __syncthreads();
    }
    if (t == 0) out_loss[0] = red[0] / (float)B_SZ;
}

// ---------------------------------------------------------------------------
extern "C" void kernel_launch(void* const* d_in, const int* in_sizes, int n_in,
                              void* d_out, int out_size) {
    const int*   label = (const int*)d_in[0];
    const float* table = (const float*)d_in[1];
    const float* W     = (const float*)d_in[2];
    const float* b     = (const float*)d_in[3];
    float* out = (float*)d_out;

    float* out_logits = out;
    float* out_loss   = out + (size_t)B_SZ * L_SZ;
    float* out_embed  = out + (size_t)B_SZ * L_SZ + 1;

    prep_kernel<<<(B_SZ + 255) / 256, 256>>>(label, table, out_embed);
    dim3 grid(GX, MSPLIT);
    logits_kernel<<<grid, NTHREADS>>>(W, b, out_logits);
    rowsum_terms_kernel<<<(B_SZ + 255) / 256, 256>>>(label, out_logits);
    loss_reduce_kernel<<<1, 1024>>>(out_loss);
}

// round 13
// speedup vs baseline: 1.0544x; 1.0250x over previous
#include <cuda_runtime.h>
#include <cuda_bf16.h>
#include <cstdint>

#define B_SZ   2048
#define L_SZ   200000
#define H_SZ   64

#define BM 128
#define BN 128
#define NTHREADS 256
#define GX ((L_SZ + BN - 1) / BN)   // 1563
#define NY (B_SZ / BM)              // 16
#define TILE_BYTES (BM * 128)       // 16384

#define SWZ128(off) ((off) ^ (((off) >> 3) & 0x70))

// exp(0.5+0.5t) ~= C0 + C1*t + C2*t^2 on |t|<~0.35 (loss-only path)
#define EXP_C0 1.6487212707f
#define EXP_C1 0.8243606354f
#define EXP_C2 0.2060901588f

__device__ float g_partial[(size_t)GX * B_SZ];
__device__ float g_terms[B_SZ];
__device__ __align__(16) uint4 g_atile[B_SZ * 8];   // pre-swizzled bf16 A tiles, 262KB

// ---------------------------------------------------------------------------
__device__ __forceinline__ uint32_t smem_u32(const void* p) {
    uint32_t a;
    asm("{ .reg .u64 t; cvta.to.shared.u64 t, %1; cvt.u32.u64 %0, t; }"
        : "=r"(a) : "l"(p));
    return a;
}
__device__ __forceinline__ void ldm_x4(uint32_t& r0, uint32_t& r1,
                                       uint32_t& r2, uint32_t& r3, uint32_t addr) {
    asm volatile("ldmatrix.sync.aligned.m8n8.x4.shared.b16 {%0,%1,%2,%3}, [%4];"
                 : "=r"(r0), "=r"(r1), "=r"(r2), "=r"(r3) : "r"(addr));
}
__device__ __forceinline__ void ldm_x2(uint32_t& r0, uint32_t& r1, uint32_t addr) {
    asm volatile("ldmatrix.sync.aligned.m8n8.x2.shared.b16 {%0,%1}, [%2];"
                 : "=r"(r0), "=r"(r1) : "r"(addr));
}
__device__ __forceinline__ void mma_bf16(float* d, const uint32_t* a, const uint32_t* bfr) {
    asm volatile(
        "mma.sync.aligned.m16n8k16.row.col.f32.bf16.bf16.f32 "
        "{%0,%1,%2,%3}, {%4,%5,%6,%7}, {%8,%9}, {%0,%1,%2,%3};"
        : "+f"(d[0]), "+f"(d[1]), "+f"(d[2]), "+f"(d[3])
        : "r"(a[0]), "r"(a[1]), "r"(a[2]), "r"(a[3]), "r"(bfr[0]), "r"(bfr[1]));
}
__device__ __forceinline__ float htanh(float v) {
    float t;
    asm("tanh.approx.f32 %0, %1;" : "=f"(t) : "f"(v));
    return t;
}
__device__ __forceinline__ uint4 pack_bf16(float4 v0, float4 v1) {
    uint4 u;
    __nv_bfloat162 t;
    t = __float22bfloat162_rn(make_float2(v0.x, v0.y)); u.x = *(uint32_t*)&t;
    t = __float22bfloat162_rn(make_float2(v0.z, v0.w)); u.y = *(uint32_t*)&t;
    t = __float22bfloat162_rn(make_float2(v1.x, v1.y)); u.z = *(uint32_t*)&t;
    t = __float22bfloat162_rn(make_float2(v1.z, v1.w)); u.w = *(uint32_t*)&t;
    return u;
}

#define CP_ASYNC16(dst, src) \
    asm volatile("cp.async.cg.shared.global [%0], [%1], 16;" :: "r"(dst), "l"(src))
#define CP_COMMIT() asm volatile("cp.async.commit_group;" ::: "memory")
#define CP_WAIT(n)  asm volatile("cp.async.wait_group %0;" :: "n"(n) : "memory")

// ---------------------------------------------------------------------------
// Kernel 1: gather return_embed + build pre-swizzled bf16 A tiles.
// ---------------------------------------------------------------------------
__global__ void prep_kernel(const int* __restrict__ label,
                            const float* __restrict__ table,
                            float* __restrict__ out_embed) {
    int m = blockIdx.x * blockDim.x + threadIdx.x;
    if (m >= B_SZ) return;
    int lab = label[m];
    const float4* src = reinterpret_cast<const float4*>(table + (size_t)lab * H_SZ);
    float* dst = out_embed + (size_t)m * H_SZ;

    char* tile = reinterpret_cast<char*>(g_atile) + (m >> 7) * TILE_BYTES;
    int r = m & 127;
    #pragma unroll
    for (int ch = 0; ch < 8; ch++) {
        float4 v0 = __ldg(src + ch * 2);
        float4 v1 = __ldg(src + ch * 2 + 1);
        reinterpret_cast<float*>(dst)[ch * 8 + 0] = v0.x;
        reinterpret_cast<float*>(dst)[ch * 8 + 1] = v0.y;
        reinterpret_cast<float*>(dst)[ch * 8 + 2] = v0.z;
        reinterpret_cast<float*>(dst)[ch * 8 + 3] = v0.w;
        reinterpret_cast<float*>(dst)[ch * 8 + 4] = v1.x;
        reinterpret_cast<float*>(dst)[ch * 8 + 5] = v1.y;
        reinterpret_cast<float*>(dst)[ch * 8 + 6] = v1.z;
        reinterpret_cast<float*>(dst)[ch * 8 + 7] = v1.w;
        uint32_t off = r * 128 + ch * 16;
        *reinterpret_cast<uint4*>(tile + SWZ128(off)) = pack_bf16(v0, v1);
    }
}

// ---------------------------------------------------------------------------
// Kernel 2: R8 kernel exactly, except the exp-partial accumulation is
// 2 FMA/element (quadratic, constant term hoisted to the g_partial write).
// ---------------------------------------------------------------------------
__global__ __launch_bounds__(NTHREADS, 2)
void logits_kernel(const float* __restrict__ W,
                   const float* __restrict__ b,
                   float* __restrict__ out) {
    __shared__ __align__(1024) char w_s[BN * 128];
    __shared__ __align__(1024) char a_s[2][TILE_BYTES];
    __shared__ float bia_s[BN];      // b/2
    __shared__ float red_s[BM][4];

    const int tid  = threadIdx.x;
    const int wid  = tid >> 5;
    const int lane = tid & 31;
    const int bx   = blockIdx.x;
    const int nblk = bx * BN;

    int nvalid = L_SZ - nblk;
    if (nvalid > BN) nvalid = BN;
    const float c0n = EXP_C0 * (float)nvalid;   // per-row constant term

    const uint32_t w_base = smem_u32(w_s);
    const int wm = (wid & 1) * 64;
    const int wn = (wid >> 1) * 32;

    const char* atile_g = reinterpret_cast<const char*>(g_atile);

    // ---- W tile + half-bias ----
    for (int idx = tid; idx < BN * 8; idx += NTHREADS) {
        int r = idx >> 3, ch = idx & 7;
        int n = nblk + r;
        uint32_t off = r * 128 + ch * 16;
        if (n < L_SZ) {
            const float4* src = reinterpret_cast<const float4*>(W + (size_t)n * H_SZ);
            *reinterpret_cast<uint4*>(w_s + SWZ128(off)) =
                pack_bf16(__ldg(src + ch * 2), __ldg(src + ch * 2 + 1));
        } else {
            *reinterpret_cast<uint4*>(w_s + SWZ128(off)) = make_uint4(0, 0, 0, 0);
        }
    }
    for (int idx = tid; idx < BN; idx += NTHREADS) {
        int n = nblk + idx;
        bia_s[idx] = (n < L_SZ) ? 0.5f * __ldg(&b[n]) : 0.0f;
    }

    // ---- cp.async prologue: tiles 0 and 1 in flight ----
    {
        const uint32_t d0 = smem_u32(a_s[0]) + tid * 16;
        const uint32_t d1 = smem_u32(a_s[1]) + tid * 16;
        #pragma unroll
        for (int i = 0; i < 4; i++)
            CP_ASYNC16(d0 + i * NTHREADS * 16,
                       atile_g + 0 * TILE_BYTES + tid * 16 + i * NTHREADS * 16);
        CP_COMMIT();
        #pragma unroll
        for (int i = 0; i < 4; i++)
            CP_ASYNC16(d1 + i * NTHREADS * 16,
                       atile_g + 1 * TILE_BYTES + tid * 16 + i * NTHREADS * 16);
        CP_COMMIT();
    }

    float bh0[4], bh1[4];

    for (int y = 0; y < NY; y++) {
        const int mblk = y * BM;
        const int buf = y & 1;
        const uint32_t a_base = smem_u32(a_s[buf]);

        if (y < NY - 1) CP_WAIT(1); else CP_WAIT(0);
        __syncthreads();

        if (y == 0) {   // bia_s now visible
            #pragma unroll
            for (int j = 0; j < 4; j++) {
                int col = wn + j * 8 + (lane & 3) * 2;
                bh0[j] = bia_s[col];
                bh1[j] = bia_s[col + 1];
            }
        }

        // ---- MMA mainloop: 4 k-steps of 16 ----
        float acc[4][4][4];
        #pragma unroll
        for (int i = 0; i < 4; i++)
            #pragma unroll
            for (int j = 0; j < 4; j++)
                #pragma unroll
                for (int e = 0; e < 4; e++) acc[i][j][e] = 0.0f;

        #pragma unroll
        for (int ks = 0; ks < 4; ks++) {
            uint32_t a[4][4];
            #pragma unroll
            for (int i = 0; i < 4; i++) {
                uint32_t off = (uint32_t)(wm + i * 16 + (lane & 15)) * 128
                             + ks * 32 + (lane >> 4) * 16;
                ldm_x4(a[i][0], a[i][1], a[i][2], a[i][3], a_base + SWZ128(off));
            }
            uint32_t bf[4][2];
            #pragma unroll
            for (int j = 0; j < 4; j++) {
                uint32_t off = (uint32_t)(wn + j * 8 + (lane & 7)) * 128
                             + ks * 32 + ((lane >> 3) & 1) * 16;
                ldm_x2(bf[j][0], bf[j][1], w_base + SWZ128(off));
            }
            #pragma unroll
            for (int i = 0; i < 4; i++)
                #pragma unroll
                for (int j = 0; j < 4; j++)
                    mma_bf16(acc[i][j], a[i], bf[j]);
        }

        // ---- Epilogue: 4 FMA + 1 MUFU per element ----
        float ex0[4], ex1[4];
        #pragma unroll
        for (int i = 0; i < 4; i++) { ex0[i] = 0.0f; ex1[i] = 0.0f; }

        #pragma unroll
        for (int i = 0; i < 4; i++) {
            const int r0 = wm + i * 16 + (lane >> 2);
            const int r1 = r0 + 8;
            #pragma unroll
            for (int j = 0; j < 4; j++) {
                const int gn = nblk + wn + j * 8 + (lane & 3) * 2;
                float t00 = htanh(fmaf(acc[i][j][0], 0.5f, bh0[j]));
                float t01 = htanh(fmaf(acc[i][j][1], 0.5f, bh1[j]));
                float t10 = htanh(fmaf(acc[i][j][2], 0.5f, bh0[j]));
                float t11 = htanh(fmaf(acc[i][j][3], 0.5f, bh1[j]));
                if (gn < L_SZ) {
                    __stcs(reinterpret_cast<float2*>(&out[(size_t)(mblk + r0) * L_SZ + gn]),
                           make_float2(fmaf(0.5f, t00, 0.5f), fmaf(0.5f, t01, 0.5f)));
                    __stcs(reinterpret_cast<float2*>(&out[(size_t)(mblk + r1) * L_SZ + gn]),
                           make_float2(fmaf(0.5f, t10, 0.5f), fmaf(0.5f, t11, 0.5f)));
                    // exp(sig) - C0  ==  t*(C1 + C2*t); constant added once later
                    ex0[i] = fmaf(t00, fmaf(EXP_C2, t00, EXP_C1), ex0[i]);
                    ex0[i] = fmaf(t01, fmaf(EXP_C2, t01, EXP_C1), ex0[i]);
                    ex1[i] = fmaf(t10, fmaf(EXP_C2, t10, EXP_C1), ex1[i]);
                    ex1[i] = fmaf(t11, fmaf(EXP_C2, t11, EXP_C1), ex1[i]);
                }
            }
        }
        #pragma unroll
        for (int i = 0; i < 4; i++) {
            float v0 = ex0[i], v1 = ex1[i];
            v0 += __shfl_down_sync(0xffffffffu, v0, 2, 4);
            v0 += __shfl_down_sync(0xffffffffu, v0, 1, 4);
            v1 += __shfl_down_sync(0xffffffffu, v1, 2, 4);
            v1 += __shfl_down_sync(0xffffffffu, v1, 1, 4);
            if ((lane & 3) == 0) {
                red_s[wm + i * 16 + (lane >> 2)][wid >> 1]     = v0;
                red_s[wm + i * 16 + (lane >> 2) + 8][wid >> 1] = v1;
            }
        }
        __syncthreads();   // a_s[buf] reads done; red_s complete

        // ---- Prefetch tile y+2 into a_s[buf] (now free) ----
        if (y + 2 < NY) {
            const uint32_t d = smem_u32(a_s[buf]) + tid * 16;
            #pragma unroll
            for (int i = 0; i < 4; i++)
                CP_ASYNC16(d + i * NTHREADS * 16,
                           atile_g + (size_t)(y + 2) * TILE_BYTES
                                   + tid * 16 + i * NTHREADS * 16);
            CP_COMMIT();
        }

        if (tid < BM) {
            float s = red_s[tid][0] + red_s[tid][1] + red_s[tid][2] + red_s[tid][3];
            g_partial[(size_t)bx * B_SZ + mblk + tid] = s + c0n;
        }
    }
}

// ---------------------------------------------------------------------------
// Kernel 3: fused deterministic row-sum + loss terms.
// ---------------------------------------------------------------------------
__global__ void rowsum_terms_kernel(const int* __restrict__ label,
                                    const float* __restrict__ logits) {
    int m = blockIdx.x * blockDim.x + threadIdx.x;
    if (m < B_SZ) {
        float s = 0.0f;
        for (int j = 0; j < GX; j++) s += g_partial[(size_t)j * B_SZ + m];
        g_terms[m] = logf(s) - logits[(size_t)m * L_SZ + label[m]];
    }
}

__global__ void loss_reduce_kernel(float* __restrict__ out_loss) {
    __shared__ float red[1024];
    int t = threadIdx.x;
    red[t] = g_terms[t] + g_terms[t + 1024];
    __syncthreads();
    for (int off = 512; off > 0; off >>= 1) {
        if (t < off) red[t] += red[t + off];
        __syncthreads();
    }
    if (t == 0) out_loss[0] = red[0] / (float)B_SZ;
}

// ---------------------------------------------------------------------------
extern "C" void kernel_launch(void* const* d_in, const int* in_sizes, int n_in,
                              void* d_out, int out_size) {
    const int*   label = (const int*)d_in[0];
    const float* table = (const float*)d_in[1];
    const float* W     = (const float*)d_in[2];
    const float* b     = (const float*)d_in[3];
    float* out = (float*)d_out;

    float* out_logits = out;
    float* out_loss   = out + (size_t)B_SZ * L_SZ;
    float* out_embed  = out + (size_t)B_SZ * L_SZ + 1;

    prep_kernel<<<(B_SZ + 255) / 256, 256>>>(label, table, out_embed);
    logits_kernel<<<GX, NTHREADS>>>(W, b, out_logits);
    rowsum_terms_kernel<<<(B_SZ + 255) / 256, 256>>>(label, out_logits);
    loss_reduce_kernel<<<1, 1024>>>(out_loss);
}

// round 14
// speedup vs baseline: 1.0587x; 1.0041x over previous
#include <cuda_runtime.h>
#include <cuda_bf16.h>
#include <cstdint>

#define B_SZ   2048
#define L_SZ   200000
#define H_SZ   64

#define BM 128
#define BN 128
#define NTHREADS 256
#define GX ((L_SZ + BN - 1) / BN)   // 1563
#define NY (B_SZ / BM)              // 16
#define TILE_BYTES (BM * 128)       // 16384
#define NSTAGE 3

// Dynamic smem layout (from 1024-aligned base)
#define SM_W    0                    // 16384
#define SM_A    16384                // 3 * 16384 = 49152
#define SM_BIAS 65536                // 512
#define SM_RED  66048                // 2 * 128 * 4 * 4 = 4096
#define SM_DYN  70144
#define SM_ALLOC (SM_DYN + 1024)

#define SWZ128(off) ((off) ^ (((off) >> 3) & 0x70))

// exp(0.5+0.5t) ~= C0 + C1*t + C2*t^2 on |t|<~0.35 (loss-only path)
#define EXP_C0 1.6487212707f
#define EXP_C1 0.8243606354f
#define EXP_C2 0.2060901588f

__device__ float g_partial[(size_t)GX * B_SZ];
__device__ float g_terms[B_SZ];
__device__ __align__(16) uint4 g_atile[B_SZ * 8];   // pre-swizzled bf16 A tiles, 262KB

// ---------------------------------------------------------------------------
__device__ __forceinline__ uint32_t smem_u32(const void* p) {
    uint32_t a;
    asm("{ .reg .u64 t; cvta.to.shared.u64 t, %1; cvt.u32.u64 %0, t; }"
        : "=r"(a) : "l"(p));
    return a;
}
__device__ __forceinline__ void ldm_x4(uint32_t& r0, uint32_t& r1,
                                       uint32_t& r2, uint32_t& r3, uint32_t addr) {
    asm volatile("ldmatrix.sync.aligned.m8n8.x4.shared.b16 {%0,%1,%2,%3}, [%4];"
                 : "=r"(r0), "=r"(r1), "=r"(r2), "=r"(r3) : "r"(addr));
}
__device__ __forceinline__ void ldm_x2(uint32_t& r0, uint32_t& r1, uint32_t addr) {
    asm volatile("ldmatrix.sync.aligned.m8n8.x2.shared.b16 {%0,%1}, [%2];"
                 : "=r"(r0), "=r"(r1) : "r"(addr));
}
__device__ __forceinline__ void mma_bf16(float* d, const uint32_t* a, const uint32_t* bfr) {
    asm volatile(
        "mma.sync.aligned.m16n8k16.row.col.f32.bf16.bf16.f32 "
        "{%0,%1,%2,%3}, {%4,%5,%6,%7}, {%8,%9}, {%0,%1,%2,%3};"
        : "+f"(d[0]), "+f"(d[1]), "+f"(d[2]), "+f"(d[3])
        : "r"(a[0]), "r"(a[1]), "r"(a[2]), "r"(a[3]), "r"(bfr[0]), "r"(bfr[1]));
}
__device__ __forceinline__ float htanh(float v) {
    float t;
    asm("tanh.approx.f32 %0, %1;" : "=f"(t) : "f"(v));
    return t;
}
__device__ __forceinline__ uint4 pack_bf16(float4 v0, float4 v1) {
    uint4 u;
    __nv_bfloat162 t;
    t = __float22bfloat162_rn(make_float2(v0.x, v0.y)); u.x = *(uint32_t*)&t;
    t = __float22bfloat162_rn(make_float2(v0.z, v0.w)); u.y = *(uint32_t*)&t;
    t = __float22bfloat162_rn(make_float2(v1.x, v1.y)); u.z = *(uint32_t*)&t;
    t = __float22bfloat162_rn(make_float2(v1.z, v1.w)); u.w = *(uint32_t*)&t;
    return u;
}

#define CP_ASYNC16(dst, src) \
    asm volatile("cp.async.cg.shared.global [%0], [%1], 16;" :: "r"(dst), "l"(src))
#define CP_COMMIT() asm volatile("cp.async.commit_group;" ::: "memory")
#define CP_WAIT(n)  asm volatile("cp.async.wait_group %0;" :: "n"(n) : "memory")

// ---------------------------------------------------------------------------
// Kernel 1: gather return_embed + build pre-swizzled bf16 A tiles.
// ---------------------------------------------------------------------------
__global__ void prep_kernel(const int* __restrict__ label,
                            const float* __restrict__ table,
                            float* __restrict__ out_embed) {
    int m = blockIdx.x * blockDim.x + threadIdx.x;
    if (m >= B_SZ) return;
    int lab = label[m];
    const float4* src = reinterpret_cast<const float4*>(table + (size_t)lab * H_SZ);
    float* dst = out_embed + (size_t)m * H_SZ;

    char* tile = reinterpret_cast<char*>(g_atile) + (m >> 7) * TILE_BYTES;
    int r = m & 127;
    #pragma unroll
    for (int ch = 0; ch < 8; ch++) {
        float4 v0 = __ldg(src + ch * 2);
        float4 v1 = __ldg(src + ch * 2 + 1);
        reinterpret_cast<float*>(dst)[ch * 8 + 0] = v0.x;
        reinterpret_cast<float*>(dst)[ch * 8 + 1] = v0.y;
        reinterpret_cast<float*>(dst)[ch * 8 + 2] = v0.z;
        reinterpret_cast<float*>(dst)[ch * 8 + 3] = v0.w;
        reinterpret_cast<float*>(dst)[ch * 8 + 4] = v1.x;
        reinterpret_cast<float*>(dst)[ch * 8 + 5] = v1.y;
        reinterpret_cast<float*>(dst)[ch * 8 + 6] = v1.z;
        reinterpret_cast<float*>(dst)[ch * 8 + 7] = v1.w;
        uint32_t off = r * 128 + ch * 16;
        *reinterpret_cast<uint4*>(tile + SWZ128(off)) = pack_bf16(v0, v1);
    }
}

// ---------------------------------------------------------------------------
// Kernel 2: R13 loop body with ONE barrier per tile:
// 3-stage a_s (prefetch issued right after the top barrier) and
// double-buffered red_s (g_partial write deferred to next iteration's top).
// ---------------------------------------------------------------------------
extern __shared__ char dsm_raw[];

__global__ __launch_bounds__(NTHREADS, 2)
void logits_kernel(const float* __restrict__ W,
                   const float* __restrict__ b,
                   float* __restrict__ out) {
    const int tid  = threadIdx.x;
    const int wid  = tid >> 5;
    const int lane = tid & 31;
    const int bx   = blockIdx.x;
    const int nblk = bx * BN;

    int nvalid = L_SZ - nblk;
    if (nvalid > BN) nvalid = BN;
    const float c0n = EXP_C0 * (float)nvalid;   // hoisted constant term

    uint32_t raw = smem_u32(dsm_raw);
    uint32_t abase = (raw + 1023u) & ~1023u;
    char* base = dsm_raw + (abase - raw);

    char*  w_s   = base + SM_W;
    float* bia_s = reinterpret_cast<float*>(base + SM_BIAS);
    float (*red_s)[BM][4] = reinterpret_cast<float (*)[BM][4]>(base + SM_RED);

    const uint32_t w_base  = abase + SM_W;
    const uint32_t a_base0 = abase + SM_A;

    const int wm = (wid & 1) * 64;
    const int wn = (wid >> 1) * 32;

    const char* atile_g = reinterpret_cast<const char*>(g_atile);

    // ---- W tile + half-bias ----
    for (int idx = tid; idx < BN * 8; idx += NTHREADS) {
        int r = idx >> 3, ch = idx & 7;
        int n = nblk + r;
        uint32_t off = r * 128 + ch * 16;
        if (n < L_SZ) {
            const float4* src = reinterpret_cast<const float4*>(W + (size_t)n * H_SZ);
            *reinterpret_cast<uint4*>(w_s + SWZ128(off)) =
                pack_bf16(__ldg(src + ch * 2), __ldg(src + ch * 2 + 1));
        } else {
            *reinterpret_cast<uint4*>(w_s + SWZ128(off)) = make_uint4(0, 0, 0, 0);
        }
    }
    for (int idx = tid; idx < BN; idx += NTHREADS) {
        int n = nblk + idx;
        bia_s[idx] = (n < L_SZ) ? 0.5f * __ldg(&b[n]) : 0.0f;
    }

    // ---- cp.async prologue: tiles 0 and 1 in flight ----
    #pragma unroll
    for (int t = 0; t < 2; t++) {
        const uint32_t d = a_base0 + t * TILE_BYTES + tid * 16;
        #pragma unroll
        for (int i = 0; i < 4; i++)
            CP_ASYNC16(d + i * NTHREADS * 16,
                       atile_g + (size_t)t * TILE_BYTES + tid * 16 + i * NTHREADS * 16);
        CP_COMMIT();
    }

    float bh0[4], bh1[4];

    for (int y = 0; y < NY; y++) {
        const int mblk = y * BM;
        const uint32_t a_base = a_base0 + (y % NSTAGE) * TILE_BYTES;

        if (y < NY - 1) CP_WAIT(1); else CP_WAIT(0);
        __syncthreads();   // the ONLY barrier per tile

        // ---- deferred g_partial write for tile y-1 (red_s now complete) ----
        if (y > 0 && tid < BM) {
            const float* r = red_s[(y - 1) & 1][tid];
            g_partial[(size_t)bx * B_SZ + (y - 1) * BM + tid]
                = r[0] + r[1] + r[2] + r[3] + c0n;
        }

        // ---- issue prefetch for tile y+2 (stage (y+2)%3 == (y-1)%3: all
        //      warps passed the barrier, so tile y-1's reads are done) ----
        if (y + 2 < NY) {
            const uint32_t d = a_base0 + ((y + 2) % NSTAGE) * TILE_BYTES + tid * 16;
            #pragma unroll
            for (int i = 0; i < 4; i++)
                CP_ASYNC16(d + i * NTHREADS * 16,
                           atile_g + (size_t)(y + 2) * TILE_BYTES
                                   + tid * 16 + i * NTHREADS * 16);
            CP_COMMIT();
        }

        if (y == 0) {   // bia_s visible after first barrier
            #pragma unroll
            for (int j = 0; j < 4; j++) {
                int col = wn + j * 8 + (lane & 3) * 2;
                bh0[j] = bia_s[col];
                bh1[j] = bia_s[col + 1];
            }
        }

        // ---- MMA mainloop: 4 k-steps of 16 ----
        float acc[4][4][4];
        #pragma unroll
        for (int i = 0; i < 4; i++)
            #pragma unroll
            for (int j = 0; j < 4; j++)
                #pragma unroll
                for (int e = 0; e < 4; e++) acc[i][j][e] = 0.0f;

        #pragma unroll
        for (int ks = 0; ks < 4; ks++) {
            uint32_t a[4][4];
            #pragma unroll
            for (int i = 0; i < 4; i++) {
                uint32_t off = (uint32_t)(wm + i * 16 + (lane & 15)) * 128
                             + ks * 32 + (lane >> 4) * 16;
                ldm_x4(a[i][0], a[i][1], a[i][2], a[i][3], a_base + SWZ128(off));
            }
            uint32_t bf[4][2];
            #pragma unroll
            for (int j = 0; j < 4; j++) {
                uint32_t off = (uint32_t)(wn + j * 8 + (lane & 7)) * 128
                             + ks * 32 + ((lane >> 3) & 1) * 16;
                ldm_x2(bf[j][0], bf[j][1], w_base + SWZ128(off));
            }
            #pragma unroll
            for (int i = 0; i < 4; i++)
                #pragma unroll
                for (int j = 0; j < 4; j++)
                    mma_bf16(acc[i][j], a[i], bf[j]);
        }

        // ---- Epilogue (R13 form) ----
        float ex0[4], ex1[4];
        #pragma unroll
        for (int i = 0; i < 4; i++) { ex0[i] = 0.0f; ex1[i] = 0.0f; }

        #pragma unroll
        for (int i = 0; i < 4; i++) {
            const int r0 = wm + i * 16 + (lane >> 2);
            const int r1 = r0 + 8;
            #pragma unroll
            for (int j = 0; j < 4; j++) {
                const int gn = nblk + wn + j * 8 + (lane & 3) * 2;
                float t00 = htanh(fmaf(acc[i][j][0], 0.5f, bh0[j]));
                float t01 = htanh(fmaf(acc[i][j][1], 0.5f, bh1[j]));
                float t10 = htanh(fmaf(acc[i][j][2], 0.5f, bh0[j]));
                float t11 = htanh(fmaf(acc[i][j][3], 0.5f, bh1[j]));
                if (gn < L_SZ) {
                    __stcs(reinterpret_cast<float2*>(&out[(size_t)(mblk + r0) * L_SZ + gn]),
                           make_float2(fmaf(0.5f, t00, 0.5f), fmaf(0.5f, t01, 0.5f)));
                    __stcs(reinterpret_cast<float2*>(&out[(size_t)(mblk + r1) * L_SZ + gn]),
                           make_float2(fmaf(0.5f, t10, 0.5f), fmaf(0.5f, t11, 0.5f)));
                    ex0[i] = fmaf(t00, fmaf(EXP_C2, t00, EXP_C1), ex0[i]);
                    ex0[i] = fmaf(t01, fmaf(EXP_C2, t01, EXP_C1), ex0[i]);
                    ex1[i] = fmaf(t10, fmaf(EXP_C2, t10, EXP_C1), ex1[i]);
                    ex1[i] = fmaf(t11, fmaf(EXP_C2, t11, EXP_C1), ex1[i]);
                }
            }
        }
        #pragma unroll
        for (int i = 0; i < 4; i++) {
            float v0 = ex0[i], v1 = ex1[i];
            v0 += __shfl_down_sync(0xffffffffu, v0, 2, 4);
            v0 += __shfl_down_sync(0xffffffffu, v0, 1, 4);
            v1 += __shfl_down_sync(0xffffffffu, v1, 2, 4);
            v1 += __shfl_down_sync(0xffffffffu, v1, 1, 4);
            if ((lane & 3) == 0) {
                red_s[y & 1][wm + i * 16 + (lane >> 2)][wid >> 1]     = v0;
                red_s[y & 1][wm + i * 16 + (lane >> 2) + 8][wid >> 1] = v1;
            }
        }
        // no second barrier: next iteration's top barrier orders everything
    }

    // ---- final flush for tile NY-1 ----
    __syncthreads();
    if (tid < BM) {
        const float* r = red_s[(NY - 1) & 1][tid];
        g_partial[(size_t)bx * B_SZ + (NY - 1) * BM + tid]
            = r[0] + r[1] + r[2] + r[3] + c0n;
    }
}

// ---------------------------------------------------------------------------
// Kernel 3: fused deterministic row-sum + loss terms.
// ---------------------------------------------------------------------------
__global__ void rowsum_terms_kernel(const int* __restrict__ label,
                                    const float* __restrict__ logits) {
    int m = blockIdx.x * blockDim.x + threadIdx.x;
    if (m < B_SZ) {
        float s = 0.0f;
        for (int j = 0; j < GX; j++) s += g_partial[(size_t)j * B_SZ + m];
        g_terms[m] = logf(s) - logits[(size_t)m * L_SZ + label[m]];
    }
}

__global__ void loss_reduce_kernel(float* __restrict__ out_loss) {
    __shared__ float red[1024];
    int t = threadIdx.x;
    red[t] = g_terms[t] + g_terms[t + 1024];
    __syncthreads();
    for (int off = 512; off > 0; off >>= 1) {
        if (t < off) red[t] += red[t + off];
        __syncthreads();
    }
    if (t == 0) out_loss[0] = red[0] / (float)B_SZ;
}

// ---------------------------------------------------------------------------
extern "C" void kernel_launch(void* const* d_in, const int* in_sizes, int n_in,
                              void* d_out, int out_size) {
    const int*   label = (const int*)d_in[0];
    const float* table = (const float*)d_in[1];
    const float* W     = (const float*)d_in[2];
    const float* b     = (const float*)d_in[3];
    float* out = (float*)d_out;

    float* out_logits = out;
    float* out_loss   = out + (size_t)B_SZ * L_SZ;
    float* out_embed  = out + (size_t)B_SZ * L_SZ + 1;

    cudaFuncSetAttribute(logits_kernel,
                         cudaFuncAttributeMaxDynamicSharedMemorySize, SM_ALLOC);

    prep_kernel<<<(B_SZ + 255) / 256, 256>>>(label, table, out_embed);
    logits_kernel<<<GX, NTHREADS, SM_ALLOC>>>(W, b, out_logits);
    rowsum_terms_kernel<<<(B_SZ + 255) / 256, 256>>>(label, out_logits);
    loss_reduce_kernel<<<1, 1024>>>(out_loss);
}